// round 1
// baseline (speedup 1.0000x reference)
#include <cuda_runtime.h>
#include <math.h>

// ---------------- problem constants ----------------
#define S_LEN   2048
#define HID     3584
#define NHQ     16
#define NKV     8
#define DH      256
#define GROUPS  2          // NHQ / NKV
#define WINDOW  1024
#define BANDW   1152       // 9 tiles of 128
#define SOFTCAP 50.0f
#define SCALING 0.0625f    // 256^-0.5

// ---------------- device scratch (no allocations allowed) ----------------
__device__ float g_Q[(size_t)S_LEN * NHQ * DH];        // 2048 x 4096
__device__ float g_K[(size_t)S_LEN * NKV * DH];        // 2048 x 2048
__device__ float g_V[(size_t)S_LEN * NKV * DH];        // 2048 x 2048
__device__ float g_S[(size_t)NHQ * S_LEN * BANDW];     // 16 x 2048 x 1152 (151 MB)
__device__ float g_AO[(size_t)S_LEN * NHQ * DH];       // 2048 x 4096

// ---------------- 128x128x16 fp32 tile GEMM ----------------
// BT=true : C(128x128) = A(128xK, row-major lda) * B(128xK, row-major ldb)^T   (NT)
// BT=false: C(128x128) = A(128xK, row-major lda) * B(Kx128, row-major ldb)     (NN)
// A,B,C already point at the tile origin. K % 16 == 0. 256 threads.
template <bool BT>
__device__ __forceinline__ void gemm_tile128(
    const float* __restrict__ A, int lda,
    const float* __restrict__ B, int ldb,
    float* __restrict__ C, int ldc, int K)
{
    __shared__ float As[16][132];
    __shared__ float Bs[16][132];

    const int tid = threadIdx.x;
    const int tx = tid & 15;        // 0..15 -> col group of 8
    const int ty = tid >> 4;        // 0..15 -> row group of 8

    float acc[8][8];
#pragma unroll
    for (int i = 0; i < 8; ++i)
#pragma unroll
        for (int j = 0; j < 8; ++j) acc[i][j] = 0.0f;

    for (int k0 = 0; k0 < K; k0 += 16) {
        // load A tile (128 rows x 16 cols), store transposed As[k][m]
#pragma unroll
        for (int i = 0; i < 2; ++i) {
            int idx = tid + i * 256;          // 0..511 float4 slots
            int row = idx >> 2;               // 0..127
            int c4  = (idx & 3) << 2;         // 0,4,8,12
            float4 a = *(const float4*)(A + (size_t)row * lda + k0 + c4);
            As[c4 + 0][row] = a.x;
            As[c4 + 1][row] = a.y;
            As[c4 + 2][row] = a.z;
            As[c4 + 3][row] = a.w;
        }
        if (BT) {
            // B is N x K row-major: same transpose pattern -> Bs[k][n]
#pragma unroll
            for (int i = 0; i < 2; ++i) {
                int idx = tid + i * 256;
                int row = idx >> 2;           // n within tile
                int c4  = (idx & 3) << 2;
                float4 b = *(const float4*)(B + (size_t)row * ldb + k0 + c4);
                Bs[c4 + 0][row] = b.x;
                Bs[c4 + 1][row] = b.y;
                Bs[c4 + 2][row] = b.z;
                Bs[c4 + 3][row] = b.w;
            }
        } else {
            // B is K x N row-major: direct copy rows -> Bs[k][n]
#pragma unroll
            for (int i = 0; i < 2; ++i) {
                int idx = tid + i * 256;      // 0..511
                int kk  = idx >> 5;           // 0..15
                int n4  = (idx & 31) << 2;    // 0..124
                float4 b = *(const float4*)(B + (size_t)(k0 + kk) * ldb + n4);
                *(float4*)&Bs[kk][n4] = b;
            }
        }
        __syncthreads();

#pragma unroll
        for (int k = 0; k < 16; ++k) {
            float av[8], bv[8];
            float4 t0 = *(const float4*)&As[k][ty * 8];
            float4 t1 = *(const float4*)&As[k][ty * 8 + 4];
            av[0] = t0.x; av[1] = t0.y; av[2] = t0.z; av[3] = t0.w;
            av[4] = t1.x; av[5] = t1.y; av[6] = t1.z; av[7] = t1.w;
            float4 u0 = *(const float4*)&Bs[k][tx * 8];
            float4 u1 = *(const float4*)&Bs[k][tx * 8 + 4];
            bv[0] = u0.x; bv[1] = u0.y; bv[2] = u0.z; bv[3] = u0.w;
            bv[4] = u1.x; bv[5] = u1.y; bv[6] = u1.z; bv[7] = u1.w;
#pragma unroll
            for (int i = 0; i < 8; ++i)
#pragma unroll
                for (int j = 0; j < 8; ++j)
                    acc[i][j] = fmaf(av[i], bv[j], acc[i][j]);
        }
        __syncthreads();
    }

#pragma unroll
    for (int i = 0; i < 8; ++i) {
        float* cp = C + (size_t)(ty * 8 + i) * ldc + tx * 8;
        *(float4*)cp       = make_float4(acc[i][0], acc[i][1], acc[i][2], acc[i][3]);
        *(float4*)(cp + 4) = make_float4(acc[i][4], acc[i][5], acc[i][6], acc[i][7]);
    }
}

// ---------------- generic NT GEMM wrapper ----------------
__global__ void __launch_bounds__(256, 2)
k_gemm_nt(const float* __restrict__ A, int lda,
          const float* __restrict__ B, int ldb,
          float* __restrict__ C, int ldc, int K)
{
    const float* At = A + (size_t)blockIdx.y * 128 * lda;
    const float* Bt = B + (size_t)blockIdx.x * 128 * ldb;
    float* Ct = C + (size_t)blockIdx.y * 128 * ldc + (size_t)blockIdx.x * 128;
    gemm_tile128<true>(At, lda, Bt, ldb, Ct, ldc, K);
}

// ---------------- RoPE on Q and K ----------------
__global__ void __launch_bounds__(256)
k_rope(const float* __restrict__ cosb, const float* __restrict__ sinb)
{
    int idx = blockIdx.x * blockDim.x + threadIdx.x;   // S_LEN*(NHQ+NKV)*128
    int d = idx & 127;
    int t = idx >> 7;
    int slot = t % (NHQ + NKV);
    int s = t / (NHQ + NKV);

    float c0 = cosb[s * DH + d];
    float s0 = sinb[s * DH + d];
    float c1 = cosb[s * DH + d + 128];
    float s1 = sinb[s * DH + d + 128];

    float* p;
    if (slot < NHQ) p = g_Q + ((size_t)s * NHQ + slot) * DH + d;
    else            p = g_K + ((size_t)s * NKV + (slot - NHQ)) * DH + d;

    float x0 = p[0];
    float x1 = p[128];
    p[0]   = x0 * c0 - x1 * s0;   // rotate_half low half:  -x[d+128]
    p[128] = x1 * c1 + x0 * s1;   // rotate_half high half: +x[d]
}

// ---------------- banded S = Q K^T (per head) ----------------
__global__ void __launch_bounds__(256, 2)
k_attn_s()
{
    int h  = blockIdx.z;
    int r  = blockIdx.y;      // q row-tile (128 rows)
    int cx = blockIdx.x;      // 0..8 band tile
    int cbase = (r - 8 > 0) ? (r - 8) : 0;
    int ct = cbase + cx;
    if (ct > r) return;       // outside causal band (only when r < 8)

    const float* A = g_Q + (size_t)r * 128 * (NHQ * DH) + (size_t)h * DH;
    const float* B = g_K + (size_t)ct * 128 * (NKV * DH) + (size_t)(h / GROUPS) * DH;
    float* C = g_S + ((size_t)h * S_LEN + (size_t)r * 128) * BANDW + (size_t)cx * 128;
    gemm_tile128<true>(A, NHQ * DH, B, NKV * DH, C, BANDW, DH);
}

// ---------------- band softmax with softcap + mask ----------------
__global__ void __launch_bounds__(256)
k_softmax()
{
    int row  = blockIdx.x * 8 + (threadIdx.x >> 5);   // 0..32767 = h*2048+q
    int lane = threadIdx.x & 31;
    int h = row >> 11;
    int q = row & 2047;

    float* p = g_S + ((size_t)h * S_LEN + q) * BANDW;
    int r  = q >> 7;
    int c0 = ((r - 8 > 0) ? (r - 8) : 0) * 128;
    int kmin = (q - (WINDOW - 1) > 0) ? (q - (WINDOW - 1)) : 0;

    float v[36];
    float m = -1e30f;
#pragma unroll
    for (int i = 0; i < 36; ++i) {
        int j = lane + 32 * i;
        int k = c0 + j;
        float t;
        if (k >= kmin && k <= q) {
            float x = p[j] * (SCALING / SOFTCAP);
            t = SOFTCAP * tanhf(x);
        } else {
            t = -1e30f;
        }
        v[i] = t;
        m = fmaxf(m, t);
    }
#pragma unroll
    for (int o = 16; o > 0; o >>= 1)
        m = fmaxf(m, __shfl_xor_sync(0xFFFFFFFFu, m, o));

    float l = 0.0f;
#pragma unroll
    for (int i = 0; i < 36; ++i) {
        v[i] = expf(v[i] - m);    // masked -> exp(-huge) = 0
        l += v[i];
    }
#pragma unroll
    for (int o = 16; o > 0; o >>= 1)
        l += __shfl_xor_sync(0xFFFFFFFFu, l, o);

    float inv = 1.0f / l;
#pragma unroll
    for (int i = 0; i < 36; ++i)
        p[lane + 32 * i] = v[i] * inv;
}

// ---------------- banded PV: AO = P V (per head, NN) ----------------
__global__ void __launch_bounds__(256, 2)
k_attn_pv()
{
    int h  = blockIdx.z;
    int r  = blockIdx.y;      // q row-tile
    int nx = blockIdx.x;      // 0..1 output col tile of 128 (D=256)
    int c0 = ((r - 8 > 0) ? (r - 8) : 0) * 128;

    const float* A = g_S + ((size_t)h * S_LEN + (size_t)r * 128) * BANDW;
    const float* B = g_V + (size_t)c0 * (NKV * DH) + (size_t)(h / GROUPS) * DH + (size_t)nx * 128;
    float* C = g_AO + (size_t)r * 128 * (NHQ * DH) + (size_t)h * DH + (size_t)nx * 128;
    gemm_tile128<false>(A, BANDW, B, NKV * DH, C, NHQ * DH, BANDW);
}

// ---------------- launch ----------------
extern "C" void kernel_launch(void* const* d_in, const int* in_sizes, int n_in,
                              void* d_out, int out_size)
{
    const float* hs   = (const float*)d_in[0];
    const float* cosb = (const float*)d_in[1];
    const float* sinb = (const float*)d_in[2];
    const float* wq   = (const float*)d_in[3];
    const float* wk   = (const float*)d_in[4];
    const float* wv   = (const float*)d_in[5];
    const float* wo   = (const float*)d_in[6];
    float* out = (float*)d_out;

    void *qp, *kp, *vp, *aop;
    cudaGetSymbolAddress(&qp,  g_Q);
    cudaGetSymbolAddress(&kp,  g_K);
    cudaGetSymbolAddress(&vp,  g_V);
    cudaGetSymbolAddress(&aop, g_AO);
    float* Qp  = (float*)qp;
    float* Kp  = (float*)kp;
    float* Vp  = (float*)vp;
    float* AOp = (float*)aop;

    // QKV projections: C[s,o] = sum_h hs[s,h] * W[o,h]  (NT)
    k_gemm_nt<<<dim3(NHQ * DH / 128, S_LEN / 128), 256>>>(hs, HID, wq, HID, Qp, NHQ * DH, HID);
    k_gemm_nt<<<dim3(NKV * DH / 128, S_LEN / 128), 256>>>(hs, HID, wk, HID, Kp, NKV * DH, HID);
    k_gemm_nt<<<dim3(NKV * DH / 128, S_LEN / 128), 256>>>(hs, HID, wv, HID, Vp, NKV * DH, HID);

    // RoPE
    k_rope<<<(S_LEN * (NHQ + NKV) * 128) / 256, 256>>>(cosb, sinb);

    // banded scores
    k_attn_s<<<dim3(9, S_LEN / 128, NHQ), 256>>>();

    // softcap + mask + softmax over band
    k_softmax<<<(NHQ * S_LEN) / 8, 256>>>();

    // PV
    k_attn_pv<<<dim3(2, S_LEN / 128, NHQ), 256>>>();

    // output projection: out[s,hh] = sum_o AO[s,o] * wo[hh,o]  (NT)
    k_gemm_nt<<<dim3(HID / 128, S_LEN / 128), 256>>>(AOp, NHQ * DH, wo, NHQ * DH, out, HID, NHQ * DH);
}

// round 5
// speedup vs baseline: 2.5877x; 2.5877x over previous
#include <cuda_runtime.h>
#include <cuda_bf16.h>
#include <math.h>
#include <stdint.h>

// ---------------- problem constants ----------------
#define S_LEN   2048
#define HID     3584
#define NHQ     16
#define NKV     8
#define DH      256
#define GROUPS  2
#define WINDOW  1024
#define BANDW   1152
#define SOFTCAP 50.0f
#define SCALING 0.0625f

typedef __nv_bfloat16 bf16;

// ---------------- device scratch ----------------
__device__ float g_Q [(size_t)S_LEN * NHQ * DH];
__device__ float g_K [(size_t)S_LEN * NKV * DH];
__device__ float g_V [(size_t)S_LEN * NKV * DH];
__device__ float g_S [(size_t)NHQ * S_LEN * BANDW];
__device__ float g_AO[(size_t)S_LEN * NHQ * DH];

__device__ bf16 g_hsH[(size_t)S_LEN * HID],      g_hsL[(size_t)S_LEN * HID];
__device__ bf16 g_wqH[(size_t)NHQ * DH * HID],   g_wqL[(size_t)NHQ * DH * HID];
__device__ bf16 g_wkH[(size_t)NKV * DH * HID],   g_wkL[(size_t)NKV * DH * HID];
__device__ bf16 g_wvH[(size_t)NKV * DH * HID],   g_wvL[(size_t)NKV * DH * HID];
__device__ bf16 g_woH[(size_t)HID * NHQ * DH],   g_woL[(size_t)HID * NHQ * DH];
__device__ bf16 g_QH [(size_t)S_LEN * NHQ * DH], g_QL [(size_t)S_LEN * NHQ * DH];
__device__ bf16 g_KH [(size_t)S_LEN * NKV * DH], g_KL [(size_t)S_LEN * NKV * DH];
__device__ bf16 g_VtH[(size_t)NKV * DH * S_LEN], g_VtL[(size_t)NKV * DH * S_LEN];
__device__ bf16 g_PH [(size_t)NHQ * S_LEN * BANDW], g_PL[(size_t)NHQ * S_LEN * BANDW];
__device__ bf16 g_AOH[(size_t)S_LEN * NHQ * DH], g_AOL[(size_t)S_LEN * NHQ * DH];

// ---------------- helpers ----------------
__device__ __forceinline__ uint32_t smem_u32(const void* p) {
    uint32_t a;
    asm("{ .reg .u64 t; cvta.to.shared.u64 t, %1; cvt.u32.u64 %0, t; }" : "=r"(a) : "l"(p));
    return a;
}
__device__ __forceinline__ uint32_t lds32(uint32_t a) {
    uint32_t v;
    asm volatile("ld.shared.b32 %0, [%1];" : "=r"(v) : "r"(a));
    return v;
}
__device__ __forceinline__ void cp16(uint32_t saddr, const void* g) {
    asm volatile("cp.async.cg.shared.global [%0], [%1], 16;" :: "r"(saddr), "l"(g) : "memory");
}
#define CP_COMMIT() asm volatile("cp.async.commit_group;" ::: "memory")

__device__ __forceinline__ void hmma(float* c,
    uint32_t a0, uint32_t a1, uint32_t a2, uint32_t a3,
    uint32_t b0, uint32_t b1)
{
    asm volatile(
        "mma.sync.aligned.m16n8k16.row.col.f32.bf16.bf16.f32 "
        "{%0,%1,%2,%3}, {%4,%5,%6,%7}, {%8,%9}, {%0,%1,%2,%3};"
        : "+f"(c[0]), "+f"(c[1]), "+f"(c[2]), "+f"(c[3])
        : "r"(a0), "r"(a1), "r"(a2), "r"(a3), "r"(b0), "r"(b1));
}

// ---------------- cp.async stage loader ----------------
// Stage layout (32 KB): Ah[128][32] Al Bh Bl, each 8192 B, row pitch 64 B,
// 16B segments swizzled: seg_store = seg ^ ((row>>1)&3).
#define STAGE_BYTES 32768
#define SMEM_BYTES  (2 * STAGE_BYTES)

__device__ __forceinline__ void stage_cp(
    const bf16* __restrict__ Ah, const bf16* __restrict__ Al, int lda,
    const bf16* __restrict__ Bh, const bf16* __restrict__ Bl, int ldb,
    int k0, uint32_t smb, int buf, int tid)
{
    uint32_t sb = smb + buf * STAGE_BYTES;
#pragma unroll
    for (int i = 0; i < 2; ++i) {
        int si  = tid + i * 256;
        int row = si >> 2;
        int seg = si & 3;
        uint32_t soff = row * 64 + ((seg ^ ((row >> 1) & 3)) << 4);
        size_t goA = (size_t)row * lda + k0 + seg * 8;
        size_t goB = (size_t)row * ldb + k0 + seg * 8;
        cp16(sb +     0 + soff, Ah + goA);
        cp16(sb +  8192 + soff, Al + goA);
        cp16(sb + 16384 + soff, Bh + goB);
        cp16(sb + 24576 + soff, Bl + goB);
    }
}

// swizzled LDS address for logical (row, seg, within-bytes)
__device__ __forceinline__ uint32_t sw_addr(uint32_t base, int row, int seg, int w) {
    return base + row * 64 + ((seg ^ ((row >> 1) & 3)) << 4) + w;
}

// ---------------- 128x128 NT GEMM tile: C = A*B^T, split-bf16 x3 ----------------
// 256 threads (8 warps, 2x4). K % 32 == 0.
__device__ void gemm_hmma_tile(
    const bf16* __restrict__ Ah, const bf16* __restrict__ Al, int lda,
    const bf16* __restrict__ Bh, const bf16* __restrict__ Bl, int ldb,
    float* __restrict__ C, int ldc, int K)
{
    extern __shared__ char smem[];
    const uint32_t smb = smem_u32(smem);
    const int tid  = threadIdx.x;
    const int lane = tid & 31;
    const int wid  = tid >> 5;
    const int wm   = wid >> 2;        // 0..1 (64-row block)
    const int wn   = wid & 3;         // 0..3 (32-col block)
    const int g    = lane >> 2;       // 0..7
    const int t4   = lane & 3;        // 0..3

    float acc[4][4][4];
#pragma unroll
    for (int mi = 0; mi < 4; ++mi)
#pragma unroll
        for (int ni = 0; ni < 4; ++ni)
#pragma unroll
            for (int q = 0; q < 4; ++q) acc[mi][ni][q] = 0.0f;

    const int nK = K >> 5;
    stage_cp(Ah, Al, lda, Bh, Bl, ldb, 0, smb, 0, tid);
    CP_COMMIT();

    for (int ki = 0; ki < nK; ++ki) {
        if (ki + 1 < nK) {
            stage_cp(Ah, Al, lda, Bh, Bl, ldb, (ki + 1) << 5, smb, (ki + 1) & 1, tid);
            CP_COMMIT();
            asm volatile("cp.async.wait_group 1;" ::: "memory");
        } else {
            asm volatile("cp.async.wait_group 0;" ::: "memory");
        }
        __syncthreads();

        const uint32_t sA = smb + (ki & 1) * STAGE_BYTES;
        const uint32_t sAl = sA + 8192;
        const uint32_t sB  = sA + 16384;
        const uint32_t sBl = sA + 24576;

#pragma unroll
        for (int ks = 0; ks < 2; ++ks) {
            const int s0 = ks * 2, s1 = ks * 2 + 1;
            const int w = t4 * 4;

            uint32_t ah[4][4], al[4][4];
#pragma unroll
            for (int mi = 0; mi < 4; ++mi) {
                int R0 = wm * 64 + mi * 16 + g;
                int R1 = R0 + 8;
                ah[mi][0] = lds32(sw_addr(sA,  R0, s0, w));
                ah[mi][1] = lds32(sw_addr(sA,  R1, s0, w));
                ah[mi][2] = lds32(sw_addr(sA,  R0, s1, w));
                ah[mi][3] = lds32(sw_addr(sA,  R1, s1, w));
                al[mi][0] = lds32(sw_addr(sAl, R0, s0, w));
                al[mi][1] = lds32(sw_addr(sAl, R1, s0, w));
                al[mi][2] = lds32(sw_addr(sAl, R0, s1, w));
                al[mi][3] = lds32(sw_addr(sAl, R1, s1, w));
            }
            uint32_t bh[4][2], bl[4][2];
#pragma unroll
            for (int ni = 0; ni < 4; ++ni) {
                int N0 = wn * 32 + ni * 8 + g;
                bh[ni][0] = lds32(sw_addr(sB,  N0, s0, w));
                bh[ni][1] = lds32(sw_addr(sB,  N0, s1, w));
                bl[ni][0] = lds32(sw_addr(sBl, N0, s0, w));
                bl[ni][1] = lds32(sw_addr(sBl, N0, s1, w));
            }

#pragma unroll
            for (int mi = 0; mi < 4; ++mi)
#pragma unroll
                for (int ni = 0; ni < 4; ++ni) {
                    float* c = acc[mi][ni];
                    hmma(c, ah[mi][0], ah[mi][1], ah[mi][2], ah[mi][3], bh[ni][0], bh[ni][1]);
                    hmma(c, ah[mi][0], ah[mi][1], ah[mi][2], ah[mi][3], bl[ni][0], bl[ni][1]);
                    hmma(c, al[mi][0], al[mi][1], al[mi][2], al[mi][3], bh[ni][0], bh[ni][1]);
                }
        }
        __syncthreads();
    }

    // epilogue
#pragma unroll
    for (int mi = 0; mi < 4; ++mi) {
        int R0 = wm * 64 + mi * 16 + g;
        int R1 = R0 + 8;
#pragma unroll
        for (int ni = 0; ni < 4; ++ni) {
            int col = wn * 32 + ni * 8 + t4 * 2;
            float2 v0 = make_float2(acc[mi][ni][0], acc[mi][ni][1]);
            float2 v1 = make_float2(acc[mi][ni][2], acc[mi][ni][3]);
            *(float2*)(C + (size_t)R0 * ldc + col) = v0;
            *(float2*)(C + (size_t)R1 * ldc + col) = v1;
        }
    }
}

// ---------------- GEMM wrapper kernels ----------------
__global__ void __launch_bounds__(256, 1)
k_gemm_nt(const bf16* Ah, const bf16* Al, int lda,
          const bf16* Bh, const bf16* Bl, int ldb,
          float* C, int ldc, int K)
{
    size_t m0 = (size_t)blockIdx.y * 128, n0 = (size_t)blockIdx.x * 128;
    gemm_hmma_tile(Ah + m0 * lda, Al + m0 * lda, lda,
                   Bh + n0 * ldb, Bl + n0 * ldb, ldb,
                   C + m0 * ldc + n0, ldc, K);
}

__global__ void __launch_bounds__(256, 1)
k_attn_s()
{
    int h = blockIdx.z, r = blockIdx.y, cx = blockIdx.x;
    int cbase = (r - 8 > 0) ? (r - 8) : 0;
    int ct = cbase + cx;
    if (ct > r) return;
    size_t aoff = (size_t)r * 128 * (NHQ * DH) + (size_t)h * DH;
    size_t boff = (size_t)ct * 128 * (NKV * DH) + (size_t)(h / GROUPS) * DH;
    float* C = g_S + ((size_t)h * S_LEN + (size_t)r * 128) * BANDW + (size_t)cx * 128;
    gemm_hmma_tile(g_QH + aoff, g_QL + aoff, NHQ * DH,
                   g_KH + boff, g_KL + boff, NKV * DH,
                   C, BANDW, DH);
}

__global__ void __launch_bounds__(256, 1)
k_attn_pv()
{
    int h = blockIdx.z, r = blockIdx.y, nx = blockIdx.x;
    int c0 = ((r - 8 > 0) ? (r - 8) : 0) * 128;
    size_t aoff = ((size_t)h * S_LEN + (size_t)r * 128) * BANDW;
    // Vt rows are indexed by KV-head * DH + d  (h/GROUPS, NOT h)
    size_t boff = ((size_t)(h / GROUPS) * DH + (size_t)nx * 128) * S_LEN + (size_t)c0;
    float* C = g_AO + (size_t)r * 128 * (NHQ * DH) + (size_t)h * DH + (size_t)nx * 128;
    gemm_hmma_tile(g_PH + aoff, g_PL + aoff, BANDW,
                   g_VtH + boff, g_VtL + boff, S_LEN,
                   C, NHQ * DH, BANDW);
}

// ---------------- elementwise kernels ----------------
__global__ void __launch_bounds__(256)
k_split(const float* __restrict__ x, bf16* __restrict__ hi, bf16* __restrict__ lo, int n4)
{
    int i = blockIdx.x * 256 + threadIdx.x;
    if (i >= n4) return;
    float4 v = ((const float4*)x)[i];
    bf16 h0 = __float2bfloat16(v.x), h1 = __float2bfloat16(v.y);
    bf16 h2 = __float2bfloat16(v.z), h3 = __float2bfloat16(v.w);
    __nv_bfloat162 H0; H0.x = h0; H0.y = h1;
    __nv_bfloat162 H1; H1.x = h2; H1.y = h3;
    ((__nv_bfloat162*)hi)[i * 2 + 0] = H0;
    ((__nv_bfloat162*)hi)[i * 2 + 1] = H1;
    __nv_bfloat162 L0, L1;
    L0.x = __float2bfloat16(v.x - __bfloat162float(h0));
    L0.y = __float2bfloat16(v.y - __bfloat162float(h1));
    L1.x = __float2bfloat16(v.z - __bfloat162float(h2));
    L1.y = __float2bfloat16(v.w - __bfloat162float(h3));
    ((__nv_bfloat162*)lo)[i * 2 + 0] = L0;
    ((__nv_bfloat162*)lo)[i * 2 + 1] = L1;
}

__global__ void __launch_bounds__(256)
k_rope_split(const float* __restrict__ cosb, const float* __restrict__ sinb)
{
    int idx = blockIdx.x * 256 + threadIdx.x;      // S*(NHQ+NKV)*128
    int d = idx & 127;
    int t = idx >> 7;
    int slot = t % (NHQ + NKV);
    int s = t / (NHQ + NKV);

    float c0 = cosb[s * DH + d],       s0 = sinb[s * DH + d];
    float c1 = cosb[s * DH + d + 128], s1 = sinb[s * DH + d + 128];

    if (slot < NHQ) {
        size_t b = (size_t)s * (NHQ * DH) + slot * DH + d;
        float x0 = g_Q[b], x1 = g_Q[b + 128];
        float y0 = x0 * c0 - x1 * s0;
        float y1 = x1 * c1 + x0 * s1;
        bf16 h0 = __float2bfloat16(y0), h1 = __float2bfloat16(y1);
        g_QH[b] = h0;       g_QH[b + 128] = h1;
        g_QL[b] = __float2bfloat16(y0 - __bfloat162float(h0));
        g_QL[b + 128] = __float2bfloat16(y1 - __bfloat162float(h1));
    } else {
        size_t b = (size_t)s * (NKV * DH) + (slot - NHQ) * DH + d;
        float x0 = g_K[b], x1 = g_K[b + 128];
        float y0 = x0 * c0 - x1 * s0;
        float y1 = x1 * c1 + x0 * s1;
        bf16 h0 = __float2bfloat16(y0), h1 = __float2bfloat16(y1);
        g_KH[b] = h0;       g_KH[b + 128] = h1;
        g_KL[b] = __float2bfloat16(y0 - __bfloat162float(h0));
        g_KL[b + 128] = __float2bfloat16(y1 - __bfloat162float(h1));
    }
}

// V transpose: Vt[o][s] = V[s][o], split to bf16 hi/lo. V is [2048][2048].
__global__ void __launch_bounds__(256)
k_vtrans()
{
    __shared__ float t[32][33];
    int bs = blockIdx.x * 32, bo = blockIdx.y * 32;
    int tx = threadIdx.x, ty = threadIdx.y;        // 32 x 8
#pragma unroll
    for (int j = 0; j < 32; j += 8)
        t[ty + j][tx] = g_V[(size_t)(bs + ty + j) * (NKV * DH) + bo + tx];
    __syncthreads();
#pragma unroll
    for (int j = 0; j < 32; j += 8) {
        float v = t[tx][ty + j];                   // V[bs+tx][bo+ty+j]
        size_t o = (size_t)(bo + ty + j) * S_LEN + bs + tx;
        bf16 h = __float2bfloat16(v);
        g_VtH[o] = h;
        g_VtL[o] = __float2bfloat16(v - __bfloat162float(h));
    }
}

// band softmax: softcap tanh + mask + normalize; writes split-bf16 P
__global__ void __launch_bounds__(256)
k_softmax()
{
    int row  = blockIdx.x * 8 + (threadIdx.x >> 5);
    int lane = threadIdx.x & 31;
    int h = row >> 11;
    int q = row & 2047;

    size_t base = ((size_t)h * S_LEN + q) * BANDW;
    const float* p = g_S + base;
    int r  = q >> 7;
    int c0 = ((r - 8 > 0) ? (r - 8) : 0) * 128;
    int kmin = (q - (WINDOW - 1) > 0) ? (q - (WINDOW - 1)) : 0;

    float v[36];
    float m = -1e30f;
#pragma unroll
    for (int i = 0; i < 36; ++i) {
        int j = lane + 32 * i;
        int k = c0 + j;
        float tt;
        if (k >= kmin && k <= q) {
            float x = p[j] * (SCALING / SOFTCAP);
            tt = SOFTCAP * tanhf(x);
        } else {
            tt = -1e30f;
        }
        v[i] = tt;
        m = fmaxf(m, tt);
    }
#pragma unroll
    for (int o = 16; o > 0; o >>= 1)
        m = fmaxf(m, __shfl_xor_sync(0xFFFFFFFFu, m, o));

    float l = 0.0f;
#pragma unroll
    for (int i = 0; i < 36; ++i) {
        v[i] = expf(v[i] - m);
        l += v[i];
    }
#pragma unroll
    for (int o = 16; o > 0; o >>= 1)
        l += __shfl_xor_sync(0xFFFFFFFFu, l, o);

    float inv = 1.0f / l;
#pragma unroll
    for (int i = 0; i < 36; ++i) {
        float pv = v[i] * inv;
        bf16 hh = __float2bfloat16(pv);
        g_PH[base + lane + 32 * i] = hh;
        g_PL[base + lane + 32 * i] = __float2bfloat16(pv - __bfloat162float(hh));
    }
}

// ---------------- launch ----------------
extern "C" void kernel_launch(void* const* d_in, const int* in_sizes, int n_in,
                              void* d_out, int out_size)
{
    const float* hs   = (const float*)d_in[0];
    const float* cosb = (const float*)d_in[1];
    const float* sinb = (const float*)d_in[2];
    const float* wq   = (const float*)d_in[3];
    const float* wk   = (const float*)d_in[4];
    const float* wv   = (const float*)d_in[5];
    const float* wo   = (const float*)d_in[6];
    float* out = (float*)d_out;

    void *pQ, *pK, *pV, *pAO;
    void *phsH, *phsL, *pwqH, *pwqL, *pwkH, *pwkL, *pwvH, *pwvL, *pwoH, *pwoL, *pAOH, *pAOL;
    cudaGetSymbolAddress(&pQ, g_Q);   cudaGetSymbolAddress(&pK, g_K);
    cudaGetSymbolAddress(&pV, g_V);   cudaGetSymbolAddress(&pAO, g_AO);
    cudaGetSymbolAddress(&phsH, g_hsH); cudaGetSymbolAddress(&phsL, g_hsL);
    cudaGetSymbolAddress(&pwqH, g_wqH); cudaGetSymbolAddress(&pwqL, g_wqL);
    cudaGetSymbolAddress(&pwkH, g_wkH); cudaGetSymbolAddress(&pwkL, g_wkL);
    cudaGetSymbolAddress(&pwvH, g_wvH); cudaGetSymbolAddress(&pwvL, g_wvL);
    cudaGetSymbolAddress(&pwoH, g_woH); cudaGetSymbolAddress(&pwoL, g_woL);
    cudaGetSymbolAddress(&pAOH, g_AOH); cudaGetSymbolAddress(&pAOL, g_AOL);

    cudaFuncSetAttribute(k_gemm_nt, cudaFuncAttributeMaxDynamicSharedMemorySize, SMEM_BYTES);
    cudaFuncSetAttribute(k_attn_s,  cudaFuncAttributeMaxDynamicSharedMemorySize, SMEM_BYTES);
    cudaFuncSetAttribute(k_attn_pv, cudaFuncAttributeMaxDynamicSharedMemorySize, SMEM_BYTES);

    // split inputs to bf16 hi/lo
    int n4;
    n4 = S_LEN * HID / 4;      k_split<<<(n4 + 255) / 256, 256>>>(hs, (bf16*)phsH, (bf16*)phsL, n4);
    n4 = NHQ * DH * HID / 4;   k_split<<<(n4 + 255) / 256, 256>>>(wq, (bf16*)pwqH, (bf16*)pwqL, n4);
    n4 = NKV * DH * HID / 4;   k_split<<<(n4 + 255) / 256, 256>>>(wk, (bf16*)pwkH, (bf16*)pwkL, n4);
    n4 = NKV * DH * HID / 4;   k_split<<<(n4 + 255) / 256, 256>>>(wv, (bf16*)pwvH, (bf16*)pwvL, n4);
    n4 = HID * NHQ * DH / 4;   k_split<<<(n4 + 255) / 256, 256>>>(wo, (bf16*)pwoH, (bf16*)pwoL, n4);

    // QKV projections (NT)
    k_gemm_nt<<<dim3(NHQ * DH / 128, S_LEN / 128), 256, SMEM_BYTES>>>(
        (bf16*)phsH, (bf16*)phsL, HID, (bf16*)pwqH, (bf16*)pwqL, HID, (float*)pQ, NHQ * DH, HID);
    k_gemm_nt<<<dim3(NKV * DH / 128, S_LEN / 128), 256, SMEM_BYTES>>>(
        (bf16*)phsH, (bf16*)phsL, HID, (bf16*)pwkH, (bf16*)pwkL, HID, (float*)pK, NKV * DH, HID);
    k_gemm_nt<<<dim3(NKV * DH / 128, S_LEN / 128), 256, SMEM_BYTES>>>(
        (bf16*)phsH, (bf16*)phsL, HID, (bf16*)pwvH, (bf16*)pwvL, HID, (float*)pV, NKV * DH, HID);

    // RoPE + split, V transpose + split
    k_rope_split<<<(S_LEN * (NHQ + NKV) * 128) / 256, 256>>>(cosb, sinb);
    k_vtrans<<<dim3(S_LEN / 32, (NKV * DH) / 32), dim3(32, 8)>>>();

    // banded scores (HMMA)
    k_attn_s<<<dim3(9, S_LEN / 128, NHQ), 256, SMEM_BYTES>>>();

    // softcap + mask + softmax -> split-bf16 P
    k_softmax<<<(NHQ * S_LEN) / 8, 256>>>();

    // PV (HMMA)
    k_attn_pv<<<dim3(2, S_LEN / 128, NHQ), 256, SMEM_BYTES>>>();

    // AO split + output projection
    n4 = S_LEN * NHQ * DH / 4;
    k_split<<<(n4 + 255) / 256, 256>>>((const float*)pAO, (bf16*)pAOH, (bf16*)pAOL, n4);
    k_gemm_nt<<<dim3(HID / 128, S_LEN / 128), 256, SMEM_BYTES>>>(
        (bf16*)pAOH, (bf16*)pAOL, NHQ * DH, (bf16*)pwoH, (bf16*)pwoL, NHQ * DH, out, HID, NHQ * DH);
}

// round 6
// speedup vs baseline: 3.1140x; 1.2034x over previous
#include <cuda_runtime.h>
#include <cuda_bf16.h>
#include <math.h>
#include <stdint.h>

// ---------------- problem constants ----------------
#define S_LEN   2048
#define HID     3584
#define NHQ     16
#define NKV     8
#define DH      256
#define GROUPS  2
#define WINDOW  1024
#define BANDW   1152
#define SOFTCAP 50.0f
#define SCALING 0.0625f

typedef __nv_bfloat16 bf16;

// ---------------- device scratch ----------------
__device__ float g_Q [(size_t)S_LEN * NHQ * DH];
__device__ float g_K [(size_t)S_LEN * NKV * DH];
__device__ float g_V [(size_t)S_LEN * NKV * DH];
__device__ float g_S [(size_t)NHQ * S_LEN * BANDW];

__device__ bf16 g_hsH[(size_t)S_LEN * HID],      g_hsL[(size_t)S_LEN * HID];
__device__ bf16 g_wqH[(size_t)NHQ * DH * HID],   g_wqL[(size_t)NHQ * DH * HID];
__device__ bf16 g_wkH[(size_t)NKV * DH * HID],   g_wkL[(size_t)NKV * DH * HID];
__device__ bf16 g_wvH[(size_t)NKV * DH * HID],   g_wvL[(size_t)NKV * DH * HID];
__device__ bf16 g_woH[(size_t)HID * NHQ * DH],   g_woL[(size_t)HID * NHQ * DH];
__device__ bf16 g_QH [(size_t)S_LEN * NHQ * DH], g_QL [(size_t)S_LEN * NHQ * DH];
__device__ bf16 g_KH [(size_t)S_LEN * NKV * DH], g_KL [(size_t)S_LEN * NKV * DH];
__device__ bf16 g_VtH[(size_t)NKV * DH * S_LEN], g_VtL[(size_t)NKV * DH * S_LEN];
__device__ bf16 g_PH [(size_t)NHQ * S_LEN * BANDW], g_PL[(size_t)NHQ * S_LEN * BANDW];
__device__ bf16 g_AOH[(size_t)S_LEN * NHQ * DH], g_AOL[(size_t)S_LEN * NHQ * DH];

// ---------------- helpers ----------------
__device__ __forceinline__ uint32_t smem_u32(const void* p) {
    uint32_t a;
    asm("{ .reg .u64 t; cvta.to.shared.u64 t, %1; cvt.u32.u64 %0, t; }" : "=r"(a) : "l"(p));
    return a;
}
__device__ __forceinline__ void cp16(uint32_t saddr, const void* g) {
    asm volatile("cp.async.cg.shared.global [%0], [%1], 16;" :: "r"(saddr), "l"(g) : "memory");
}
#define CP_COMMIT() asm volatile("cp.async.commit_group;" ::: "memory")

#define LDSM4(r0, r1, r2, r3, addr) \
    asm volatile("ldmatrix.sync.aligned.m8n8.x4.shared.b16 {%0,%1,%2,%3}, [%4];" \
        : "=r"(r0), "=r"(r1), "=r"(r2), "=r"(r3) : "r"(addr))

__device__ __forceinline__ void hmma(float* c,
    uint32_t a0, uint32_t a1, uint32_t a2, uint32_t a3,
    uint32_t b0, uint32_t b1)
{
    asm volatile(
        "mma.sync.aligned.m16n8k16.row.col.f32.bf16.bf16.f32 "
        "{%0,%1,%2,%3}, {%4,%5,%6,%7}, {%8,%9}, {%0,%1,%2,%3};"
        : "+f"(c[0]), "+f"(c[1]), "+f"(c[2]), "+f"(c[3])
        : "r"(a0), "r"(a1), "r"(a2), "r"(a3), "r"(b0), "r"(b1));
}

// ---------------- stage layout ----------------
// Stage (32 KB): Ah[128][32] Al Bh Bl, each 8 KB, row pitch 64 B,
// 16B segments swizzled: seg_store = seg ^ ((row>>1)&3).
#define STAGE_BYTES 32768
#define NSTAGE      3
#define SMEM_BYTES  (NSTAGE * STAGE_BYTES)

__device__ __forceinline__ void stage_cp(
    const bf16* __restrict__ Ah, const bf16* __restrict__ Al, int lda,
    const bf16* __restrict__ Bh, const bf16* __restrict__ Bl, int ldb,
    int k0, uint32_t smb, int buf, int tid)
{
    uint32_t sb = smb + buf * STAGE_BYTES;
#pragma unroll
    for (int i = 0; i < 4; ++i) {
        int si  = tid + i * 128;       // 0..511 16B chunks per array
        int row = si >> 2;
        int seg = si & 3;
        uint32_t soff = row * 64 + ((seg ^ ((row >> 1) & 3)) << 4);
        size_t goA = (size_t)row * lda + k0 + seg * 8;
        size_t goB = (size_t)row * ldb + k0 + seg * 8;
        cp16(sb +     0 + soff, Ah + goA);
        cp16(sb +  8192 + soff, Al + goA);
        cp16(sb + 16384 + soff, Bh + goB);
        cp16(sb + 24576 + soff, Bl + goB);
    }
}

// ---------------- 128x128 NT GEMM tile: C = A*B^T, split-bf16 x3 ----------------
// 128 threads (4 warps, 2x2 grid, warp tile 64x64). K % 32 == 0.
// EPI=0: write fp32 C.  EPI=1: write split-bf16 (Ch, Cl).
template <int EPI>
__device__ void gemm_hmma_tile(
    const bf16* __restrict__ Ah, const bf16* __restrict__ Al, int lda,
    const bf16* __restrict__ Bh, const bf16* __restrict__ Bl, int ldb,
    float* __restrict__ C, bf16* __restrict__ Ch, bf16* __restrict__ Cl,
    int ldc, int K)
{
    extern __shared__ char smem[];
    const uint32_t smb = smem_u32(smem);
    const int tid  = threadIdx.x;
    const int lane = tid & 31;
    const int wid  = tid >> 5;
    const int wm   = wid >> 1;        // 0..1
    const int wn   = wid & 1;         // 0..1
    const int la   = lane & 7;
    const int grp  = lane >> 3;       // 0..3

    float acc[4][8][4];
#pragma unroll
    for (int mi = 0; mi < 4; ++mi)
#pragma unroll
        for (int ni = 0; ni < 8; ++ni)
#pragma unroll
            for (int q = 0; q < 4; ++q) acc[mi][ni][q] = 0.0f;

    // per-lane ldmatrix row precompute
    // A: grp0:(R+la,s0) grp1:(R+8+la,s0) grp2:(R+la,s1) grp3:(R+8+la,s1)
    uint32_t offA[4], swA[4];
#pragma unroll
    for (int mi = 0; mi < 4; ++mi) {
        int r = wm * 64 + mi * 16 + la + (grp & 1) * 8;
        offA[mi] = r * 64;
        swA[mi]  = (r >> 1) & 3;
    }
    const int segselA = grp >> 1;
    // B: grp0:(N+la,s0) grp1:(N+la,s1) grp2:(N+8+la,s0) grp3:(N+8+la,s1)
    uint32_t offB[4], swB[4];
#pragma unroll
    for (int p = 0; p < 4; ++p) {
        int r = wn * 64 + p * 16 + la + (grp >> 1) * 8;
        offB[p] = r * 64;
        swB[p]  = (r >> 1) & 3;
    }
    const int segselB = grp & 1;

    const int nK = K >> 5;
    stage_cp(Ah, Al, lda, Bh, Bl, ldb, 0, smb, 0, tid);
    CP_COMMIT();
    if (nK > 1) stage_cp(Ah, Al, lda, Bh, Bl, ldb, 32, smb, 1, tid);
    CP_COMMIT();

    int buf = 0;
    for (int ki = 0; ki < nK; ++ki) {
        __syncthreads();                      // all warps done with buf being overwritten
        if (ki + 2 < nK)
            stage_cp(Ah, Al, lda, Bh, Bl, ldb, (ki + 2) << 5, smb, (ki + 2) % NSTAGE, tid);
        CP_COMMIT();
        asm volatile("cp.async.wait_group %0;" :: "n"(2) : "memory");
        __syncthreads();                      // stage ki visible to all warps

        const uint32_t sA  = smb + buf * STAGE_BYTES;
        const uint32_t sAl = sA + 8192;
        const uint32_t sB  = sA + 16384;
        const uint32_t sBl = sA + 24576;

#pragma unroll
        for (int ks = 0; ks < 2; ++ks) {
            uint32_t ah[4][4], al[4][4];
#pragma unroll
            for (int mi = 0; mi < 4; ++mi) {
                uint32_t aoff = offA[mi] + ((((uint32_t)(ks * 2 + segselA) ^ swA[mi])) << 4);
                LDSM4(ah[mi][0], ah[mi][1], ah[mi][2], ah[mi][3], sA + aoff);
                LDSM4(al[mi][0], al[mi][1], al[mi][2], al[mi][3], sAl + aoff);
            }
#pragma unroll
            for (int p = 0; p < 4; ++p) {
                uint32_t boff = offB[p] + ((((uint32_t)(ks * 2 + segselB) ^ swB[p])) << 4);
                uint32_t bh0, bh1, bh2, bh3, bl0, bl1, bl2, bl3;
                LDSM4(bh0, bh1, bh2, bh3, sB  + boff);
                LDSM4(bl0, bl1, bl2, bl3, sBl + boff);
#pragma unroll
                for (int mi = 0; mi < 4; ++mi) {
                    float* c0 = acc[mi][2 * p];
                    float* c1 = acc[mi][2 * p + 1];
                    hmma(c0, ah[mi][0], ah[mi][1], ah[mi][2], ah[mi][3], bh0, bh1);
                    hmma(c0, ah[mi][0], ah[mi][1], ah[mi][2], ah[mi][3], bl0, bl1);
                    hmma(c0, al[mi][0], al[mi][1], al[mi][2], al[mi][3], bh0, bh1);
                    hmma(c1, ah[mi][0], ah[mi][1], ah[mi][2], ah[mi][3], bh2, bh3);
                    hmma(c1, ah[mi][0], ah[mi][1], ah[mi][2], ah[mi][3], bl2, bl3);
                    hmma(c1, al[mi][0], al[mi][1], al[mi][2], al[mi][3], bh2, bh3);
                }
            }
        }
        buf = (buf + 1) % NSTAGE;
    }

    // epilogue
    const int g  = lane >> 2;
    const int t4 = lane & 3;
#pragma unroll
    for (int mi = 0; mi < 4; ++mi) {
        int R0 = wm * 64 + mi * 16 + g;
        int R1 = R0 + 8;
#pragma unroll
        for (int ni = 0; ni < 8; ++ni) {
            int col = wn * 64 + ni * 8 + t4 * 2;
            float* a = acc[mi][ni];
            if (EPI == 0) {
                *(float2*)(C + (size_t)R0 * ldc + col) = make_float2(a[0], a[1]);
                *(float2*)(C + (size_t)R1 * ldc + col) = make_float2(a[2], a[3]);
            } else {
                __nv_bfloat162 h0, h1, l0, l1;
                h0.x = __float2bfloat16(a[0]); h0.y = __float2bfloat16(a[1]);
                h1.x = __float2bfloat16(a[2]); h1.y = __float2bfloat16(a[3]);
                l0.x = __float2bfloat16(a[0] - __bfloat162float(h0.x));
                l0.y = __float2bfloat16(a[1] - __bfloat162float(h0.y));
                l1.x = __float2bfloat16(a[2] - __bfloat162float(h1.x));
                l1.y = __float2bfloat16(a[3] - __bfloat162float(h1.y));
                *(__nv_bfloat162*)(Ch + (size_t)R0 * ldc + col) = h0;
                *(__nv_bfloat162*)(Ch + (size_t)R1 * ldc + col) = h1;
                *(__nv_bfloat162*)(Cl + (size_t)R0 * ldc + col) = l0;
                *(__nv_bfloat162*)(Cl + (size_t)R1 * ldc + col) = l1;
            }
        }
    }
}

// ---------------- GEMM wrapper kernels ----------------
__global__ void __launch_bounds__(128, 1)
k_gemm_nt(const bf16* Ah, const bf16* Al, int lda,
          const bf16* Bh, const bf16* Bl, int ldb,
          float* C, int ldc, int K)
{
    size_t m0 = (size_t)blockIdx.y * 128, n0 = (size_t)blockIdx.x * 128;
    gemm_hmma_tile<0>(Ah + m0 * lda, Al + m0 * lda, lda,
                      Bh + n0 * ldb, Bl + n0 * ldb, ldb,
                      C + m0 * ldc + n0, nullptr, nullptr, ldc, K);
}

__global__ void __launch_bounds__(128, 1)
k_attn_s()
{
    int h = blockIdx.z, r = blockIdx.y, cx = blockIdx.x;
    int cbase = (r - 8 > 0) ? (r - 8) : 0;
    int ct = cbase + cx;
    if (ct > r) return;
    size_t aoff = (size_t)r * 128 * (NHQ * DH) + (size_t)h * DH;
    size_t boff = (size_t)ct * 128 * (NKV * DH) + (size_t)(h / GROUPS) * DH;
    float* C = g_S + ((size_t)h * S_LEN + (size_t)r * 128) * BANDW + (size_t)cx * 128;
    gemm_hmma_tile<0>(g_QH + aoff, g_QL + aoff, NHQ * DH,
                      g_KH + boff, g_KL + boff, NKV * DH,
                      C, nullptr, nullptr, BANDW, DH);
}

__global__ void __launch_bounds__(128, 1)
k_attn_pv()
{
    int h = blockIdx.z, r = blockIdx.y, nx = blockIdx.x;
    int c0 = ((r - 8 > 0) ? (r - 8) : 0) * 128;
    size_t aoff = ((size_t)h * S_LEN + (size_t)r * 128) * BANDW;
    // Vt rows indexed by KV-head (h/GROUPS)
    size_t boff = ((size_t)(h / GROUPS) * DH + (size_t)nx * 128) * S_LEN + (size_t)c0;
    size_t coff = (size_t)r * 128 * (NHQ * DH) + (size_t)h * DH + (size_t)nx * 128;
    gemm_hmma_tile<1>(g_PH + aoff, g_PL + aoff, BANDW,
                      g_VtH + boff, g_VtL + boff, S_LEN,
                      nullptr, g_AOH + coff, g_AOL + coff, NHQ * DH, BANDW);
}

// ---------------- elementwise kernels ----------------
__global__ void __launch_bounds__(256)
k_split(const float* __restrict__ x, bf16* __restrict__ hi, bf16* __restrict__ lo, int n4)
{
    int i = blockIdx.x * 256 + threadIdx.x;
    if (i >= n4) return;
    float4 v = ((const float4*)x)[i];
    bf16 h0 = __float2bfloat16(v.x), h1 = __float2bfloat16(v.y);
    bf16 h2 = __float2bfloat16(v.z), h3 = __float2bfloat16(v.w);
    __nv_bfloat162 H0; H0.x = h0; H0.y = h1;
    __nv_bfloat162 H1; H1.x = h2; H1.y = h3;
    ((__nv_bfloat162*)hi)[i * 2 + 0] = H0;
    ((__nv_bfloat162*)hi)[i * 2 + 1] = H1;
    __nv_bfloat162 L0, L1;
    L0.x = __float2bfloat16(v.x - __bfloat162float(h0));
    L0.y = __float2bfloat16(v.y - __bfloat162float(h1));
    L1.x = __float2bfloat16(v.z - __bfloat162float(h2));
    L1.y = __float2bfloat16(v.w - __bfloat162float(h3));
    ((__nv_bfloat162*)lo)[i * 2 + 0] = L0;
    ((__nv_bfloat162*)lo)[i * 2 + 1] = L1;
}

__global__ void __launch_bounds__(256)
k_rope_split(const float* __restrict__ cosb, const float* __restrict__ sinb)
{
    int idx = blockIdx.x * 256 + threadIdx.x;
    int d = idx & 127;
    int t = idx >> 7;
    int slot = t % (NHQ + NKV);
    int s = t / (NHQ + NKV);

    float c0 = cosb[s * DH + d],       s0 = sinb[s * DH + d];
    float c1 = cosb[s * DH + d + 128], s1 = sinb[s * DH + d + 128];

    if (slot < NHQ) {
        size_t b = (size_t)s * (NHQ * DH) + slot * DH + d;
        float x0 = g_Q[b], x1 = g_Q[b + 128];
        float y0 = x0 * c0 - x1 * s0;
        float y1 = x1 * c1 + x0 * s1;
        bf16 h0 = __float2bfloat16(y0), h1 = __float2bfloat16(y1);
        g_QH[b] = h0;       g_QH[b + 128] = h1;
        g_QL[b] = __float2bfloat16(y0 - __bfloat162float(h0));
        g_QL[b + 128] = __float2bfloat16(y1 - __bfloat162float(h1));
    } else {
        size_t b = (size_t)s * (NKV * DH) + (slot - NHQ) * DH + d;
        float x0 = g_K[b], x1 = g_K[b + 128];
        float y0 = x0 * c0 - x1 * s0;
        float y1 = x1 * c1 + x0 * s1;
        bf16 h0 = __float2bfloat16(y0), h1 = __float2bfloat16(y1);
        g_KH[b] = h0;       g_KH[b + 128] = h1;
        g_KL[b] = __float2bfloat16(y0 - __bfloat162float(h0));
        g_KL[b + 128] = __float2bfloat16(y1 - __bfloat162float(h1));
    }
}

// V transpose: Vt[o][s] = V[s][o], split to bf16 hi/lo.
__global__ void __launch_bounds__(256)
k_vtrans()
{
    __shared__ float t[32][33];
    int bs = blockIdx.x * 32, bo = blockIdx.y * 32;
    int tx = threadIdx.x, ty = threadIdx.y;
#pragma unroll
    for (int j = 0; j < 32; j += 8)
        t[ty + j][tx] = g_V[(size_t)(bs + ty + j) * (NKV * DH) + bo + tx];
    __syncthreads();
#pragma unroll
    for (int j = 0; j < 32; j += 8) {
        float v = t[tx][ty + j];
        size_t o = (size_t)(bo + ty + j) * S_LEN + bs + tx;
        bf16 h = __float2bfloat16(v);
        g_VtH[o] = h;
        g_VtL[o] = __float2bfloat16(v - __bfloat162float(h));
    }
}

// band softmax: softcap tanh + mask + normalize -> split-bf16 P
__global__ void __launch_bounds__(256)
k_softmax()
{
    int row  = blockIdx.x * 8 + (threadIdx.x >> 5);
    int lane = threadIdx.x & 31;
    int h = row >> 11;
    int q = row & 2047;

    size_t base = ((size_t)h * S_LEN + q) * BANDW;
    const float* p = g_S + base;
    int r  = q >> 7;
    int c0 = ((r - 8 > 0) ? (r - 8) : 0) * 128;
    int kmin = (q - (WINDOW - 1) > 0) ? (q - (WINDOW - 1)) : 0;

    float v[36];
    float m = -1e30f;
#pragma unroll
    for (int i = 0; i < 36; ++i) {
        int j = lane + 32 * i;
        int k = c0 + j;
        float tt;
        if (k >= kmin && k <= q) {
            float x = p[j] * (SCALING / SOFTCAP);
            tt = SOFTCAP * tanhf(x);
        } else {
            tt = -1e30f;
        }
        v[i] = tt;
        m = fmaxf(m, tt);
    }
#pragma unroll
    for (int o = 16; o > 0; o >>= 1)
        m = fmaxf(m, __shfl_xor_sync(0xFFFFFFFFu, m, o));

    float l = 0.0f;
#pragma unroll
    for (int i = 0; i < 36; ++i) {
        v[i] = expf(v[i] - m);
        l += v[i];
    }
#pragma unroll
    for (int o = 16; o > 0; o >>= 1)
        l += __shfl_xor_sync(0xFFFFFFFFu, l, o);

    float inv = 1.0f / l;
#pragma unroll
    for (int i = 0; i < 36; ++i) {
        float pv = v[i] * inv;
        bf16 hh = __float2bfloat16(pv);
        g_PH[base + lane + 32 * i] = hh;
        g_PL[base + lane + 32 * i] = __float2bfloat16(pv - __bfloat162float(hh));
    }
}

// ---------------- launch ----------------
extern "C" void kernel_launch(void* const* d_in, const int* in_sizes, int n_in,
                              void* d_out, int out_size)
{
    const float* hs   = (const float*)d_in[0];
    const float* cosb = (const float*)d_in[1];
    const float* sinb = (const float*)d_in[2];
    const float* wq   = (const float*)d_in[3];
    const float* wk   = (const float*)d_in[4];
    const float* wv   = (const float*)d_in[5];
    const float* wo   = (const float*)d_in[6];
    float* out = (float*)d_out;

    void *pQ, *pK, *pV;
    void *phsH, *phsL, *pwqH, *pwqL, *pwkH, *pwkL, *pwvH, *pwvL, *pwoH, *pwoL, *pAOH, *pAOL;
    cudaGetSymbolAddress(&pQ, g_Q);   cudaGetSymbolAddress(&pK, g_K);
    cudaGetSymbolAddress(&pV, g_V);
    cudaGetSymbolAddress(&phsH, g_hsH); cudaGetSymbolAddress(&phsL, g_hsL);
    cudaGetSymbolAddress(&pwqH, g_wqH); cudaGetSymbolAddress(&pwqL, g_wqL);
    cudaGetSymbolAddress(&pwkH, g_wkH); cudaGetSymbolAddress(&pwkL, g_wkL);
    cudaGetSymbolAddress(&pwvH, g_wvH); cudaGetSymbolAddress(&pwvL, g_wvL);
    cudaGetSymbolAddress(&pwoH, g_woH); cudaGetSymbolAddress(&pwoL, g_woL);
    cudaGetSymbolAddress(&pAOH, g_AOH); cudaGetSymbolAddress(&pAOL, g_AOL);

    cudaFuncSetAttribute(k_gemm_nt, cudaFuncAttributeMaxDynamicSharedMemorySize, SMEM_BYTES);
    cudaFuncSetAttribute(k_attn_s,  cudaFuncAttributeMaxDynamicSharedMemorySize, SMEM_BYTES);
    cudaFuncSetAttribute(k_attn_pv, cudaFuncAttributeMaxDynamicSharedMemorySize, SMEM_BYTES);

    // split inputs to bf16 hi/lo
    int n4;
    n4 = S_LEN * HID / 4;      k_split<<<(n4 + 255) / 256, 256>>>(hs, (bf16*)phsH, (bf16*)phsL, n4);
    n4 = NHQ * DH * HID / 4;   k_split<<<(n4 + 255) / 256, 256>>>(wq, (bf16*)pwqH, (bf16*)pwqL, n4);
    n4 = NKV * DH * HID / 4;   k_split<<<(n4 + 255) / 256, 256>>>(wk, (bf16*)pwkH, (bf16*)pwkL, n4);
    n4 = NKV * DH * HID / 4;   k_split<<<(n4 + 255) / 256, 256>>>(wv, (bf16*)pwvH, (bf16*)pwvL, n4);
    n4 = HID * NHQ * DH / 4;   k_split<<<(n4 + 255) / 256, 256>>>(wo, (bf16*)pwoH, (bf16*)pwoL, n4);

    // QKV projections (NT)
    k_gemm_nt<<<dim3(NHQ * DH / 128, S_LEN / 128), 128, SMEM_BYTES>>>(
        (bf16*)phsH, (bf16*)phsL, HID, (bf16*)pwqH, (bf16*)pwqL, HID, (float*)pQ, NHQ * DH, HID);
    k_gemm_nt<<<dim3(NKV * DH / 128, S_LEN / 128), 128, SMEM_BYTES>>>(
        (bf16*)phsH, (bf16*)phsL, HID, (bf16*)pwkH, (bf16*)pwkL, HID, (float*)pK, NKV * DH, HID);
    k_gemm_nt<<<dim3(NKV * DH / 128, S_LEN / 128), 128, SMEM_BYTES>>>(
        (bf16*)phsH, (bf16*)phsL, HID, (bf16*)pwvH, (bf16*)pwvL, HID, (float*)pV, NKV * DH, HID);

    // RoPE + split, V transpose + split
    k_rope_split<<<(S_LEN * (NHQ + NKV) * 128) / 256, 256>>>(cosb, sinb);
    k_vtrans<<<dim3(S_LEN / 32, (NKV * DH) / 32), dim3(32, 8)>>>();

    // banded scores (HMMA)
    k_attn_s<<<dim3(9, S_LEN / 128, NHQ), 128, SMEM_BYTES>>>();

    // softcap + mask + softmax -> split-bf16 P
    k_softmax<<<(NHQ * S_LEN) / 8, 256>>>();

    // PV (HMMA) — epilogue writes split-bf16 AO directly
    k_attn_pv<<<dim3(2, S_LEN / 128, NHQ), 128, SMEM_BYTES>>>();

    // output projection
    k_gemm_nt<<<dim3(HID / 128, S_LEN / 128), 128, SMEM_BYTES>>>(
        (bf16*)pAOH, (bf16*)pAOL, NHQ * DH, (bf16*)pwoH, (bf16*)pwoL, NHQ * DH, out, HID, NHQ * DH);
}

// round 7
// speedup vs baseline: 3.1182x; 1.0014x over previous
#include <cuda_runtime.h>
#include <cuda_bf16.h>
#include <math.h>
#include <stdint.h>

// ---------------- problem constants ----------------
#define S_LEN   2048
#define HID     3584
#define NHQ     16
#define NKV     8
#define DH      256
#define GROUPS  2
#define WINDOW  1024
#define BANDW   1152
#define SOFTCAP 50.0f
#define SCALING 0.0625f

typedef __nv_bfloat16 bf16;

// ---------------- device scratch ----------------
__device__ float g_Q [(size_t)S_LEN * NHQ * DH];
__device__ float g_K [(size_t)S_LEN * NKV * DH];
__device__ float g_V [(size_t)S_LEN * NKV * DH];
__device__ float g_S [(size_t)NHQ * S_LEN * BANDW];

__device__ bf16 g_hsH[(size_t)S_LEN * HID],      g_hsL[(size_t)S_LEN * HID];
__device__ bf16 g_wqH[(size_t)NHQ * DH * HID],   g_wqL[(size_t)NHQ * DH * HID];
__device__ bf16 g_wkH[(size_t)NKV * DH * HID],   g_wkL[(size_t)NKV * DH * HID];
__device__ bf16 g_wvH[(size_t)NKV * DH * HID],   g_wvL[(size_t)NKV * DH * HID];
__device__ bf16 g_woH[(size_t)HID * NHQ * DH],   g_woL[(size_t)HID * NHQ * DH];
__device__ bf16 g_QH [(size_t)S_LEN * NHQ * DH], g_QL [(size_t)S_LEN * NHQ * DH];
__device__ bf16 g_KH [(size_t)S_LEN * NKV * DH], g_KL [(size_t)S_LEN * NKV * DH];
__device__ bf16 g_VtH[(size_t)NKV * DH * S_LEN], g_VtL[(size_t)NKV * DH * S_LEN];
__device__ bf16 g_PH [(size_t)NHQ * S_LEN * BANDW], g_PL[(size_t)NHQ * S_LEN * BANDW];
__device__ bf16 g_AOH[(size_t)S_LEN * NHQ * DH], g_AOL[(size_t)S_LEN * NHQ * DH];

// ---------------- helpers ----------------
__device__ __forceinline__ uint32_t smem_u32(const void* p) {
    uint32_t a;
    asm("{ .reg .u64 t; cvta.to.shared.u64 t, %1; cvt.u32.u64 %0, t; }" : "=r"(a) : "l"(p));
    return a;
}
__device__ __forceinline__ void cp16(uint32_t saddr, const void* g) {
    asm volatile("cp.async.cg.shared.global [%0], [%1], 16;" :: "r"(saddr), "l"(g) : "memory");
}
#define CP_COMMIT() asm volatile("cp.async.commit_group;" ::: "memory")

#define LDSM4(r0, r1, r2, r3, addr) \
    asm volatile("ldmatrix.sync.aligned.m8n8.x4.shared.b16 {%0,%1,%2,%3}, [%4];" \
        : "=r"(r0), "=r"(r1), "=r"(r2), "=r"(r3) : "r"(addr))

__device__ __forceinline__ void hmma(float* c,
    uint32_t a0, uint32_t a1, uint32_t a2, uint32_t a3,
    uint32_t b0, uint32_t b1)
{
    asm volatile(
        "mma.sync.aligned.m16n8k16.row.col.f32.bf16.bf16.f32 "
        "{%0,%1,%2,%3}, {%4,%5,%6,%7}, {%8,%9}, {%0,%1,%2,%3};"
        : "+f"(c[0]), "+f"(c[1]), "+f"(c[2]), "+f"(c[3])
        : "r"(a0), "r"(a1), "r"(a2), "r"(a3), "r"(b0), "r"(b1));
}

// ---------------- stage layout ----------------
// Stage (32 KB): Ah[128][32] Al Bh Bl, each 8 KB, row pitch 64 B,
// 16B segments swizzled: seg_store = seg ^ ((row>>1)&3).
#define STAGE_BYTES 32768
#define NSTAGE      3
#define SMEM_BYTES  (NSTAGE * STAGE_BYTES)

__device__ __forceinline__ void stage_cp(
    const bf16* __restrict__ Ah, const bf16* __restrict__ Al, int lda,
    const bf16* __restrict__ Bh, const bf16* __restrict__ Bl, int ldb,
    int k0, uint32_t smb, int buf, int tid)
{
    uint32_t sb = smb + buf * STAGE_BYTES;
#pragma unroll
    for (int i = 0; i < 4; ++i) {
        int si  = tid + i * 128;       // 0..511 16B chunks per array
        int row = si >> 2;
        int seg = si & 3;
        uint32_t soff = row * 64 + ((seg ^ ((row >> 1) & 3)) << 4);
        size_t goA = (size_t)row * lda + k0 + seg * 8;
        size_t goB = (size_t)row * ldb + k0 + seg * 8;
        cp16(sb +     0 + soff, Ah + goA);
        cp16(sb +  8192 + soff, Al + goA);
        cp16(sb + 16384 + soff, Bh + goB);
        cp16(sb + 24576 + soff, Bl + goB);
    }
}

// ---------------- 128x128 NT GEMM tile: C = A*B^T, split-bf16 x3 ----------------
// 128 threads (4 warps, 2x2 grid, warp tile 64x64). K % 32 == 0.
// EPI=0: write fp32 C.  EPI=1: write split-bf16 (Ch, Cl).
template <int EPI>
__device__ void gemm_hmma_tile(
    const bf16* __restrict__ Ah, const bf16* __restrict__ Al, int lda,
    const bf16* __restrict__ Bh, const bf16* __restrict__ Bl, int ldb,
    float* __restrict__ C, bf16* __restrict__ Ch, bf16* __restrict__ Cl,
    int ldc, int K)
{
    extern __shared__ char smem[];
    const uint32_t smb = smem_u32(smem);
    const int tid  = threadIdx.x;
    const int lane = tid & 31;
    const int wid  = tid >> 5;
    const int wm   = wid >> 1;        // 0..1
    const int wn   = wid & 1;         // 0..1
    const int la   = lane & 7;
    const int grp  = lane >> 3;       // 0..3

    float acc[4][8][4];
#pragma unroll
    for (int mi = 0; mi < 4; ++mi)
#pragma unroll
        for (int ni = 0; ni < 8; ++ni)
#pragma unroll
            for (int q = 0; q < 4; ++q) acc[mi][ni][q] = 0.0f;

    // per-lane ldmatrix row precompute
    uint32_t offA[4], swA[4];
#pragma unroll
    for (int mi = 0; mi < 4; ++mi) {
        int r = wm * 64 + mi * 16 + la + (grp & 1) * 8;
        offA[mi] = r * 64;
        swA[mi]  = (r >> 1) & 3;
    }
    const int segselA = grp >> 1;
    uint32_t offB[4], swB[4];
#pragma unroll
    for (int p = 0; p < 4; ++p) {
        int r = wn * 64 + p * 16 + la + (grp >> 1) * 8;
        offB[p] = r * 64;
        swB[p]  = (r >> 1) & 3;
    }
    const int segselB = grp & 1;

    const int nK = K >> 5;
    stage_cp(Ah, Al, lda, Bh, Bl, ldb, 0, smb, 0, tid);
    CP_COMMIT();
    if (nK > 1) stage_cp(Ah, Al, lda, Bh, Bl, ldb, 32, smb, 1, tid);
    CP_COMMIT();

    int buf = 0;
    for (int ki = 0; ki < nK; ++ki) {
        __syncthreads();                      // all warps done with buf being overwritten
        if (ki + 2 < nK)
            stage_cp(Ah, Al, lda, Bh, Bl, ldb, (ki + 2) << 5, smb, (ki + 2) % NSTAGE, tid);
        CP_COMMIT();
        asm volatile("cp.async.wait_group %0;" :: "n"(2) : "memory");
        __syncthreads();                      // stage ki visible to all warps

        const uint32_t sA  = smb + buf * STAGE_BYTES;
        const uint32_t sAl = sA + 8192;
        const uint32_t sB  = sA + 16384;
        const uint32_t sBl = sA + 24576;

#pragma unroll
        for (int ks = 0; ks < 2; ++ks) {
            uint32_t ah[4][4], al[4][4];
#pragma unroll
            for (int mi = 0; mi < 4; ++mi) {
                uint32_t aoff = offA[mi] + ((((uint32_t)(ks * 2 + segselA) ^ swA[mi])) << 4);
                LDSM4(ah[mi][0], ah[mi][1], ah[mi][2], ah[mi][3], sA + aoff);
                LDSM4(al[mi][0], al[mi][1], al[mi][2], al[mi][3], sAl + aoff);
            }
#pragma unroll
            for (int p = 0; p < 4; ++p) {
                uint32_t boff = offB[p] + ((((uint32_t)(ks * 2 + segselB) ^ swB[p])) << 4);
                uint32_t bh0, bh1, bh2, bh3, bl0, bl1, bl2, bl3;
                LDSM4(bh0, bh1, bh2, bh3, sB  + boff);
                LDSM4(bl0, bl1, bl2, bl3, sBl + boff);
#pragma unroll
                for (int mi = 0; mi < 4; ++mi) {
                    float* c0 = acc[mi][2 * p];
                    float* c1 = acc[mi][2 * p + 1];
                    hmma(c0, ah[mi][0], ah[mi][1], ah[mi][2], ah[mi][3], bh0, bh1);
                    hmma(c0, ah[mi][0], ah[mi][1], ah[mi][2], ah[mi][3], bl0, bl1);
                    hmma(c0, al[mi][0], al[mi][1], al[mi][2], al[mi][3], bh0, bh1);
                    hmma(c1, ah[mi][0], ah[mi][1], ah[mi][2], ah[mi][3], bh2, bh3);
                    hmma(c1, ah[mi][0], ah[mi][1], ah[mi][2], ah[mi][3], bl2, bl3);
                    hmma(c1, al[mi][0], al[mi][1], al[mi][2], al[mi][3], bh2, bh3);
                }
            }
        }
        buf = (buf + 1) % NSTAGE;
    }

    // epilogue
    const int g  = lane >> 2;
    const int t4 = lane & 3;
#pragma unroll
    for (int mi = 0; mi < 4; ++mi) {
        int R0 = wm * 64 + mi * 16 + g;
        int R1 = R0 + 8;
#pragma unroll
        for (int ni = 0; ni < 8; ++ni) {
            int col = wn * 64 + ni * 8 + t4 * 2;
            float* a = acc[mi][ni];
            if (EPI == 0) {
                *(float2*)(C + (size_t)R0 * ldc + col) = make_float2(a[0], a[1]);
                *(float2*)(C + (size_t)R1 * ldc + col) = make_float2(a[2], a[3]);
            } else {
                __nv_bfloat162 h0, h1, l0, l1;
                h0.x = __float2bfloat16(a[0]); h0.y = __float2bfloat16(a[1]);
                h1.x = __float2bfloat16(a[2]); h1.y = __float2bfloat16(a[3]);
                l0.x = __float2bfloat16(a[0] - __bfloat162float(h0.x));
                l0.y = __float2bfloat16(a[1] - __bfloat162float(h0.y));
                l1.x = __float2bfloat16(a[2] - __bfloat162float(h1.x));
                l1.y = __float2bfloat16(a[3] - __bfloat162float(h1.y));
                *(__nv_bfloat162*)(Ch + (size_t)R0 * ldc + col) = h0;
                *(__nv_bfloat162*)(Ch + (size_t)R1 * ldc + col) = h1;
                *(__nv_bfloat162*)(Cl + (size_t)R0 * ldc + col) = l0;
                *(__nv_bfloat162*)(Cl + (size_t)R1 * ldc + col) = l1;
            }
        }
    }
}

// ---------------- GEMM wrapper kernels (2 CTAs/SM) ----------------
__global__ void __launch_bounds__(128, 2)
k_gemm_nt(const bf16* Ah, const bf16* Al, int lda,
          const bf16* Bh, const bf16* Bl, int ldb,
          float* C, int ldc, int K)
{
    size_t m0 = (size_t)blockIdx.y * 128, n0 = (size_t)blockIdx.x * 128;
    gemm_hmma_tile<0>(Ah + m0 * lda, Al + m0 * lda, lda,
                      Bh + n0 * ldb, Bl + n0 * ldb, ldb,
                      C + m0 * ldc + n0, nullptr, nullptr, ldc, K);
}

__global__ void __launch_bounds__(128, 2)
k_attn_s()
{
    int h = blockIdx.z, r = blockIdx.y, cx = blockIdx.x;
    int cbase = (r - 8 > 0) ? (r - 8) : 0;
    int ct = cbase + cx;
    if (ct > r) return;
    size_t aoff = (size_t)r * 128 * (NHQ * DH) + (size_t)h * DH;
    size_t boff = (size_t)ct * 128 * (NKV * DH) + (size_t)(h / GROUPS) * DH;
    float* C = g_S + ((size_t)h * S_LEN + (size_t)r * 128) * BANDW + (size_t)cx * 128;
    gemm_hmma_tile<0>(g_QH + aoff, g_QL + aoff, NHQ * DH,
                      g_KH + boff, g_KL + boff, NKV * DH,
                      C, nullptr, nullptr, BANDW, DH);
}

__global__ void __launch_bounds__(128, 2)
k_attn_pv()
{
    int h = blockIdx.z, r = blockIdx.y, nx = blockIdx.x;
    int c0 = ((r - 8 > 0) ? (r - 8) : 0) * 128;
    size_t aoff = ((size_t)h * S_LEN + (size_t)r * 128) * BANDW;
    // Vt rows indexed by KV-head (h/GROUPS)
    size_t boff = ((size_t)(h / GROUPS) * DH + (size_t)nx * 128) * S_LEN + (size_t)c0;
    size_t coff = (size_t)r * 128 * (NHQ * DH) + (size_t)h * DH + (size_t)nx * 128;
    gemm_hmma_tile<1>(g_PH + aoff, g_PL + aoff, BANDW,
                      g_VtH + boff, g_VtL + boff, S_LEN,
                      nullptr, g_AOH + coff, g_AOL + coff, NHQ * DH, BANDW);
}

// ---------------- elementwise kernels ----------------
__global__ void __launch_bounds__(256)
k_split(const float* __restrict__ x, bf16* __restrict__ hi, bf16* __restrict__ lo, int n4)
{
    int i = blockIdx.x * 256 + threadIdx.x;
    if (i >= n4) return;
    float4 v = ((const float4*)x)[i];
    bf16 h0 = __float2bfloat16(v.x), h1 = __float2bfloat16(v.y);
    bf16 h2 = __float2bfloat16(v.z), h3 = __float2bfloat16(v.w);
    __nv_bfloat162 H0; H0.x = h0; H0.y = h1;
    __nv_bfloat162 H1; H1.x = h2; H1.y = h3;
    ((__nv_bfloat162*)hi)[i * 2 + 0] = H0;
    ((__nv_bfloat162*)hi)[i * 2 + 1] = H1;
    __nv_bfloat162 L0, L1;
    L0.x = __float2bfloat16(v.x - __bfloat162float(h0));
    L0.y = __float2bfloat16(v.y - __bfloat162float(h1));
    L1.x = __float2bfloat16(v.z - __bfloat162float(h2));
    L1.y = __float2bfloat16(v.w - __bfloat162float(h3));
    ((__nv_bfloat162*)lo)[i * 2 + 0] = L0;
    ((__nv_bfloat162*)lo)[i * 2 + 1] = L1;
}

__global__ void __launch_bounds__(256)
k_rope_split(const float* __restrict__ cosb, const float* __restrict__ sinb)
{
    int idx = blockIdx.x * 256 + threadIdx.x;
    int d = idx & 127;
    int t = idx >> 7;
    int slot = t % (NHQ + NKV);
    int s = t / (NHQ + NKV);

    float c0 = cosb[s * DH + d],       s0 = sinb[s * DH + d];
    float c1 = cosb[s * DH + d + 128], s1 = sinb[s * DH + d + 128];

    if (slot < NHQ) {
        size_t b = (size_t)s * (NHQ * DH) + slot * DH + d;
        float x0 = g_Q[b], x1 = g_Q[b + 128];
        float y0 = x0 * c0 - x1 * s0;
        float y1 = x1 * c1 + x0 * s1;
        bf16 h0 = __float2bfloat16(y0), h1 = __float2bfloat16(y1);
        g_QH[b] = h0;       g_QH[b + 128] = h1;
        g_QL[b] = __float2bfloat16(y0 - __bfloat162float(h0));
        g_QL[b + 128] = __float2bfloat16(y1 - __bfloat162float(h1));
    } else {
        size_t b = (size_t)s * (NKV * DH) + (slot - NHQ) * DH + d;
        float x0 = g_K[b], x1 = g_K[b + 128];
        float y0 = x0 * c0 - x1 * s0;
        float y1 = x1 * c1 + x0 * s1;
        bf16 h0 = __float2bfloat16(y0), h1 = __float2bfloat16(y1);
        g_KH[b] = h0;       g_KH[b + 128] = h1;
        g_KL[b] = __float2bfloat16(y0 - __bfloat162float(h0));
        g_KL[b + 128] = __float2bfloat16(y1 - __bfloat162float(h1));
    }
}

// V transpose: Vt[o][s] = V[s][o], split to bf16 hi/lo.
__global__ void __launch_bounds__(256)
k_vtrans()
{
    __shared__ float t[32][33];
    int bs = blockIdx.x * 32, bo = blockIdx.y * 32;
    int tx = threadIdx.x, ty = threadIdx.y;
#pragma unroll
    for (int j = 0; j < 32; j += 8)
        t[ty + j][tx] = g_V[(size_t)(bs + ty + j) * (NKV * DH) + bo + tx];
    __syncthreads();
#pragma unroll
    for (int j = 0; j < 32; j += 8) {
        float v = t[tx][ty + j];
        size_t o = (size_t)(bo + ty + j) * S_LEN + bs + tx;
        bf16 h = __float2bfloat16(v);
        g_VtH[o] = h;
        g_VtL[o] = __float2bfloat16(v - __bfloat162float(h));
    }
}

// band softmax: softcap tanh + mask + normalize -> split-bf16 P
__global__ void __launch_bounds__(256)
k_softmax()
{
    int row  = blockIdx.x * 8 + (threadIdx.x >> 5);
    int lane = threadIdx.x & 31;
    int h = row >> 11;
    int q = row & 2047;

    size_t base = ((size_t)h * S_LEN + q) * BANDW;
    const float* p = g_S + base;
    int r  = q >> 7;
    int c0 = ((r - 8 > 0) ? (r - 8) : 0) * 128;
    int kmin = (q - (WINDOW - 1) > 0) ? (q - (WINDOW - 1)) : 0;

    float v[36];
    float m = -1e30f;
#pragma unroll
    for (int i = 0; i < 36; ++i) {
        int j = lane + 32 * i;
        int k = c0 + j;
        float tt;
        if (k >= kmin && k <= q) {
            float x = p[j] * (SCALING / SOFTCAP);
            tt = SOFTCAP * tanhf(x);
        } else {
            tt = -1e30f;
        }
        v[i] = tt;
        m = fmaxf(m, tt);
    }
#pragma unroll
    for (int o = 16; o > 0; o >>= 1)
        m = fmaxf(m, __shfl_xor_sync(0xFFFFFFFFu, m, o));

    float l = 0.0f;
#pragma unroll
    for (int i = 0; i < 36; ++i) {
        v[i] = expf(v[i] - m);
        l += v[i];
    }
#pragma unroll
    for (int o = 16; o > 0; o >>= 1)
        l += __shfl_xor_sync(0xFFFFFFFFu, l, o);

    float inv = 1.0f / l;
#pragma unroll
    for (int i = 0; i < 36; ++i) {
        float pv = v[i] * inv;
        bf16 hh = __float2bfloat16(pv);
        g_PH[base + lane + 32 * i] = hh;
        g_PL[base + lane + 32 * i] = __float2bfloat16(pv - __bfloat162float(hh));
    }
}

// ---------------- launch ----------------
extern "C" void kernel_launch(void* const* d_in, const int* in_sizes, int n_in,
                              void* d_out, int out_size)
{
    const float* hs   = (const float*)d_in[0];
    const float* cosb = (const float*)d_in[1];
    const float* sinb = (const float*)d_in[2];
    const float* wq   = (const float*)d_in[3];
    const float* wk   = (const float*)d_in[4];
    const float* wv   = (const float*)d_in[5];
    const float* wo   = (const float*)d_in[6];
    float* out = (float*)d_out;

    void *pQ, *pK, *pV;
    void *phsH, *phsL, *pwqH, *pwqL, *pwkH, *pwkL, *pwvH, *pwvL, *pwoH, *pwoL, *pAOH, *pAOL;
    cudaGetSymbolAddress(&pQ, g_Q);   cudaGetSymbolAddress(&pK, g_K);
    cudaGetSymbolAddress(&pV, g_V);
    cudaGetSymbolAddress(&phsH, g_hsH); cudaGetSymbolAddress(&phsL, g_hsL);
    cudaGetSymbolAddress(&pwqH, g_wqH); cudaGetSymbolAddress(&pwqL, g_wqL);
    cudaGetSymbolAddress(&pwkH, g_wkH); cudaGetSymbolAddress(&pwkL, g_wkL);
    cudaGetSymbolAddress(&pwvH, g_wvH); cudaGetSymbolAddress(&pwvL, g_wvL);
    cudaGetSymbolAddress(&pwoH, g_woH); cudaGetSymbolAddress(&pwoL, g_woL);
    cudaGetSymbolAddress(&pAOH, g_AOH); cudaGetSymbolAddress(&pAOL, g_AOL);

    cudaFuncSetAttribute(k_gemm_nt, cudaFuncAttributeMaxDynamicSharedMemorySize, SMEM_BYTES);
    cudaFuncSetAttribute(k_attn_s,  cudaFuncAttributeMaxDynamicSharedMemorySize, SMEM_BYTES);
    cudaFuncSetAttribute(k_attn_pv, cudaFuncAttributeMaxDynamicSharedMemorySize, SMEM_BYTES);

    // split inputs to bf16 hi/lo
    int n4;
    n4 = S_LEN * HID / 4;      k_split<<<(n4 + 255) / 256, 256>>>(hs, (bf16*)phsH, (bf16*)phsL, n4);
    n4 = NHQ * DH * HID / 4;   k_split<<<(n4 + 255) / 256, 256>>>(wq, (bf16*)pwqH, (bf16*)pwqL, n4);
    n4 = NKV * DH * HID / 4;   k_split<<<(n4 + 255) / 256, 256>>>(wk, (bf16*)pwkH, (bf16*)pwkL, n4);
    n4 = NKV * DH * HID / 4;   k_split<<<(n4 + 255) / 256, 256>>>(wv, (bf16*)pwvH, (bf16*)pwvL, n4);
    n4 = HID * NHQ * DH / 4;   k_split<<<(n4 + 255) / 256, 256>>>(wo, (bf16*)pwoH, (bf16*)pwoL, n4);

    // QKV projections (NT)
    k_gemm_nt<<<dim3(NHQ * DH / 128, S_LEN / 128), 128, SMEM_BYTES>>>(
        (bf16*)phsH, (bf16*)phsL, HID, (bf16*)pwqH, (bf16*)pwqL, HID, (float*)pQ, NHQ * DH, HID);
    k_gemm_nt<<<dim3(NKV * DH / 128, S_LEN / 128), 128, SMEM_BYTES>>>(
        (bf16*)phsH, (bf16*)phsL, HID, (bf16*)pwkH, (bf16*)pwkL, HID, (float*)pK, NKV * DH, HID);
    k_gemm_nt<<<dim3(NKV * DH / 128, S_LEN / 128), 128, SMEM_BYTES>>>(
        (bf16*)phsH, (bf16*)phsL, HID, (bf16*)pwvH, (bf16*)pwvL, HID, (float*)pV, NKV * DH, HID);

    // RoPE + split, V transpose + split
    k_rope_split<<<(S_LEN * (NHQ + NKV) * 128) / 256, 256>>>(cosb, sinb);
    k_vtrans<<<dim3(S_LEN / 32, (NKV * DH) / 32), dim3(32, 8)>>>();

    // banded scores (HMMA)
    k_attn_s<<<dim3(9, S_LEN / 128, NHQ), 128, SMEM_BYTES>>>();

    // softcap + mask + softmax -> split-bf16 P
    k_softmax<<<(NHQ * S_LEN) / 8, 256>>>();

    // PV (HMMA) — epilogue writes split-bf16 AO directly
    k_attn_pv<<<dim3(2, S_LEN / 128, NHQ), 128, SMEM_BYTES>>>();

    // output projection
    k_gemm_nt<<<dim3(HID / 128, S_LEN / 128), 128, SMEM_BYTES>>>(
        (bf16*)pAOH, (bf16*)pAOL, NHQ * DH, (bf16*)pwoH, (bf16*)pwoL, NHQ * DH, out, HID, NHQ * DH);
}